// round 17
// baseline (speedup 1.0000x reference)
#include <cuda_runtime.h>

#define BATCH   64
#define N       128
#define LAYERS  128
#define L2N     (LAYERS / 2)
#define STEEP   10.0f
#define INV_PI  0.318309886183790671538f
#define FULL    0xffffffffu

// Consumer-ready coefficients, indexed [batch][L2][m], m = 0..15 (col group 8m..8m+7):
//   E[m]  = {al[4m], al[4m+1], al[4m+2], al[4m+3]}        even-layer alphas
//   O[m]  = {am[4m], am[4m+1], am[4m+2], b1z[m]}          odd intra alphas + right-cross coeff
//   Bp[m] = bpz[m]                                         left-cross coeff
__device__ float4 g_E [BATCH * L2N * 16];
__device__ float4 g_O [BATCH * L2N * 16];
__device__ float  g_Bp[BATCH * L2N * 16];

// fast alpha = atan(STEEP*(b-a))/pi + 0.5, Estrin deg-11 odd minimax, abs err ~1e-5
static __device__ __forceinline__ float fast_alpha(float a, float b) {
    float y  = STEEP * (b - a);
    float ay = fabsf(y);
    float r  = __frcp_rn(y);
    float t  = (ay > 1.0f) ? r : y;
    float z  = t * t;
    float z2 = z * z;
    float z4 = z2 * z2;
    float pa_ = fmaf(z, -0.33262347f,  0.99997726f);
    float pb_ = fmaf(z, -0.11643287f,  0.19354346f);
    float pc_ = fmaf(z, -0.0117212f,   0.05265332f);
    float p   = fmaf(pc_, z4, fmaf(pb_, z2, pa_)) * t;
    float rr  = (ay > 1.0f) ? (copysignf(1.57079632679f, y) - p) : p;
    return fmaf(rr, INV_PI, 0.5f);
}

// ---------------------------------------------------------------------------
// Kernel A: one warp per batch, lane l owns x[4l..4l+3]. Halo ghosts keep all
// shuffles OFF the serial critical path (ghost even-updates recomputed locally,
// bit-exact). Emits consumer-layout coefficients via off-path scalar stores.
// ---------------------------------------------------------------------------
__global__ __launch_bounds__(32) void alpha_kernel(const float* __restrict__ in,
                                                   float* __restrict__ out_x) {
    const int b = blockIdx.x;
    const int l = threadIdx.x;
    const int m = l >> 1;

    const float4 xi = ((const float4*)(in + b * N))[l];
    float x0 = xi.x, x1 = xi.y, x2 = xi.z, x3 = xi.w;

    float4* Ee = g_E  + (size_t)b * L2N * 16;
    float4* Oo = g_O  + (size_t)b * L2N * 16;
    float*  Bp = g_Bp + (size_t)b * L2N * 16;

    #pragma unroll 2
    for (int L2 = 0; L2 < L2N; ++L2) {
        // ghost refresh (pre-even values -> off the chain)
        float gr0 = __shfl_down_sync(FULL, x0, 1);
        float gr1 = __shfl_down_sync(FULL, x1, 1);
        float gl2 = __shfl_up_sync  (FULL, x2, 1);
        float gl3 = __shfl_up_sync  (FULL, x3, 1);

        // ---- even layer ----
        float al0 = fast_alpha(x0, x1);
        float al1 = fast_alpha(x2, x3);
        float agr = fast_alpha(gr0, gr1);
        float agl = fast_alpha(gl2, gl3);
        float d0 = x0 - x1, d1 = x2 - x3;
        float n0 = fmaf(al0, d0, x1);
        float n1 = fmaf(-al0, d0, x0);
        float n2 = fmaf(al1, d1, x3);
        float n3 = fmaf(-al1, d1, x2);
        float gr0n = fmaf(agr, gr0 - gr1, gr1);   // neighbor's new x0 (bit-exact)
        float gl3n = fmaf(-agl, gl2 - gl3, gl2);  // prev neighbor's new x3
        x0 = n0; x1 = n1; x2 = n2; x3 = n3;

        // ---- odd layer (fully local) ----
        float am   = fast_alpha(x1, x2);
        float ac   = fast_alpha(x3, gr0n);   // pair (4l+3, 4l+4)
        float apre = fast_alpha(gl3n, x0);   // pair (4l-1, 4l), == prev lane's ac
        float dm  = x1 - x2;
        float nx1 = fmaf(am, dm, x2);
        float nx2 = fmaf(-am, dm, x1);
        float b1  = (l == 31) ? 0.0f : (1.0f - ac);
        float bp  = (l == 0)  ? 0.0f : (1.0f - apre);
        x3 = fmaf(b1, gr0n - x3, x3);   // no-op lane 31
        x0 = fmaf(bp, gl3n - x0, x0);   // no-op lane 0
        x1 = nx1; x2 = nx2;

        // ---- coefficient stores (off critical path) ----
        const int idx = L2 * 16 + m;
        if ((l & 1) == 0) {
            ((float2*)&Ee[idx])[0] = make_float2(al0, al1); // E.xy = al[4m], al[4m+1]
            ((float2*)&Oo[idx])[0] = make_float2(am, ac);   // O.xy = am[4m], am[4m+1]
            Bp[idx] = bp;                                   // bpz[m] (0 at m=0)
        } else {
            ((float2*)&Ee[idx])[1] = make_float2(al0, al1); // E.zw = al[4m+2], al[4m+3]
            ((float2*)&Oo[idx])[1] = make_float2(am, b1);   // O.zw = am[4m+2], b1z[m]
        }
    }

    ((float4*)(out_x + b * N))[l] = make_float4(x0, x1, x2, x3);
}

// ---------------------------------------------------------------------------
// Kernel B: half-warp layout. Lane = (h, m): half h owns one row, m = col
// group, lane holds cols 8m..8m+7 in 8 regs. Warp covers 2 rows; the odd-layer
// boundary shuffles are width-16, so ONE shuffle serves both rows:
// 2 SHFL + 3 LDS per warp per 2 layers (was 4 SHFL + 2 LDS).
// grid = BATCH*8 CTAs x 256 threads (16 rows per CTA).
// ---------------------------------------------------------------------------
__global__ __launch_bounds__(256) void mix_kernel(float* __restrict__ out_X) {
    __shared__ float4 Es [L2N * 16];   // 16 KB
    __shared__ float4 Os [L2N * 16];   // 16 KB
    __shared__ float  Bps[L2N * 16];   //  4 KB

    const int b   = blockIdx.x >> 3;
    const int grp = blockIdx.x & 7;
    const int tid = threadIdx.x;

    {
        const float4* srcE = g_E + (size_t)b * L2N * 16;
        const float4* srcO = g_O + (size_t)b * L2N * 16;
        #pragma unroll
        for (int i = 0; i < L2N * 16 / 256; ++i) {
            Es[tid + i * 256] = srcE[tid + i * 256];
            Os[tid + i * 256] = srcO[tid + i * 256];
        }
        const float4* srcB = (const float4*)(g_Bp + (size_t)b * L2N * 16);
        ((float4*)Bps)[tid] = srcB[tid];
    }
    __syncthreads();

    const int warp = tid >> 5;
    const int lane = tid & 31;
    const int h    = lane >> 4;
    const int m    = lane & 15;
    const int row  = grp * 16 + warp * 2 + h;

    // identity: lane holds cols 8m..8m+7 of `row`
    float c0 = (row == 8 * m + 0) ? 1.0f : 0.0f;
    float c1 = (row == 8 * m + 1) ? 1.0f : 0.0f;
    float c2 = (row == 8 * m + 2) ? 1.0f : 0.0f;
    float c3 = (row == 8 * m + 3) ? 1.0f : 0.0f;
    float c4 = (row == 8 * m + 4) ? 1.0f : 0.0f;
    float c5 = (row == 8 * m + 5) ? 1.0f : 0.0f;
    float c6 = (row == 8 * m + 6) ? 1.0f : 0.0f;
    float c7 = (row == 8 * m + 7) ? 1.0f : 0.0f;

    #pragma unroll 4
    for (int L2 = 0; L2 < L2N; ++L2) {
        float4 E  = Es [L2 * 16 + m];
        float4 O  = Os [L2 * 16 + m];
        float  bp = Bps[L2 * 16 + m];

        // ---- even layer: pairs (c0,c1|E.x) (c2,c3|E.y) (c4,c5|E.z) (c6,c7|E.w) ----
        {
            float d = c0 - c1; float t = fmaf(E.x, d, c1); c1 = fmaf(-E.x, d, c0); c0 = t;
        }
        {
            float d = c2 - c3; float t = fmaf(E.y, d, c3); c3 = fmaf(-E.y, d, c2); c2 = t;
        }
        {
            float d = c4 - c5; float t = fmaf(E.z, d, c5); c5 = fmaf(-E.z, d, c4); c4 = t;
        }
        {
            float d = c6 - c7; float t = fmaf(E.w, d, c7); c7 = fmaf(-E.w, d, c6); c6 = t;
        }

        // ---- odd layer ----
        float nb = __shfl_down_sync(FULL, c0, 1, 16);  // next m's col 8m+8 (old)
        float pa = __shfl_up_sync  (FULL, c7, 1, 16);  // prev m's col 8m-1 (old)
        {
            float d = c1 - c2; float t = fmaf(O.x, d, c2); c2 = fmaf(-O.x, d, c1); c1 = t;
        }
        {
            float d = c3 - c4; float t = fmaf(O.y, d, c4); c4 = fmaf(-O.y, d, c3); c3 = t;
        }
        {
            float d = c5 - c6; float t = fmaf(O.z, d, c6); c6 = fmaf(-O.z, d, c5); c5 = t;
        }
        c7 = fmaf(O.w, nb - c7, c7);   // cross right; no-op at m=15 (b1z=0)
        c0 = fmaf(bp,  pa - c0, c0);   // cross left;  no-op at m=0  (bpz=0)
    }

    float* outp = out_X + (size_t)b * N * N + (size_t)row * N + 8 * m;
    ((float4*)outp)[0] = make_float4(c0, c1, c2, c3);
    ((float4*)outp)[1] = make_float4(c4, c5, c6, c7);
}

extern "C" void kernel_launch(void* const* d_in, const int* in_sizes, int n_in,
                              void* d_out, int out_size) {
    (void)in_sizes; (void)n_in; (void)out_size;
    const float* vec = (const float*)d_in[0];
    float* out = (float*)d_out;

    // output layout: [x (64*128)] then [X (64*128*128)]
    alpha_kernel<<<BATCH, 32>>>(vec, out);
    mix_kernel<<<BATCH * 8, 256>>>(out + BATCH * N);
}